// round 11
// baseline (speedup 1.0000x reference)
#include <cuda_runtime.h>
#include <cuda_pipeline.h>

static constexpr int H = 512;
static constexpr int W = 512;
static constexpr unsigned FULL = 0xFFFFFFFFu;

static constexpr int NROWS = 10;    // input rows per stage (8 output rows + halo)
static constexpr int SSTRIDE = 520; // 4 pad + 512 data + 4 pad
static constexpr int DATA0 = 4;     // first data column in a smem row

__device__ __forceinline__ float med3f(float a, float b, float c) {
    return fmaxf(fminf(a, b), fminf(fmaxf(a, b), c));
}

// Horizontal merge for 8 outputs of one row. lo/md/hi: [L-edge, 8 own, R-edge].
__device__ __forceinline__ void hmerge8(const float* lo, const float* md,
                                         const float* hi, float* o) {
#pragma unroll
    for (int k = 0; k < 4; k++) {
        float pxl = fmaxf(lo[2 * k + 1], lo[2 * k + 2]);
        float pzl = fminf(hi[2 * k + 1], hi[2 * k + 2]);
        float mn  = fminf(md[2 * k + 1], md[2 * k + 2]);
        float mx  = fmaxf(md[2 * k + 1], md[2 * k + 2]);
        float X0 = fmaxf(lo[2 * k], pxl);
        float X1 = fmaxf(pxl, lo[2 * k + 3]);
        float Z0 = fminf(hi[2 * k], pzl);
        float Z1 = fminf(pzl, hi[2 * k + 3]);
        float Y0 = fmaxf(mn, fminf(mx, md[2 * k]));
        float Y1 = fmaxf(mn, fminf(mx, md[2 * k + 3]));
        o[2 * k]     = med3f(X0, Y0, Z0);
        o[2 * k + 1] = med3f(X1, Y1, Z1);
    }
}

__device__ __forceinline__ void do_row(const float* t, const float* p, const float* q,
                                        float et, float ep, float eq,
                                        bool isL, bool isR,
                                        float* __restrict__ orow, int c0) {
    float lo[10], md[10], hi[10];
#pragma unroll
    for (int i = 0; i < 8; i++) {
        float m = fmaxf(t[i], p[i]);
        lo[i + 1] = fminf(t[i], p[i]);
        hi[i + 1] = fmaxf(m, q[i]);
        md[i + 1] = fminf(m, q[i]);
    }
    float em = fmaxf(et, ep);
    float elo = fminf(et, ep), ehi = fmaxf(em, eq), emd = fminf(em, eq);
    float Ll = __shfl_up_sync(FULL, lo[8], 1);
    float Lm = __shfl_up_sync(FULL, md[8], 1);
    float Lh = __shfl_up_sync(FULL, hi[8], 1);
    float Rl = __shfl_down_sync(FULL, lo[1], 1);
    float Rm = __shfl_down_sync(FULL, md[1], 1);
    float Rh = __shfl_down_sync(FULL, hi[1], 1);
    lo[0] = isL ? elo : Ll;  md[0] = isL ? emd : Lm;  hi[0] = isL ? ehi : Lh;
    lo[9] = isR ? elo : Rl;  md[9] = isR ? emd : Rm;  hi[9] = isR ? ehi : Rh;
    float o[8];
    hmerge8(lo, md, hi, o);
    *(float4*)(orow + c0)     = make_float4(o[0], o[1], o[2], o[3]);
    *(float4*)(orow + c0 + 4) = make_float4(o[4], o[5], o[6], o[7]);
}

__global__ __launch_bounds__(128)
void median3x3_kernel(const float* __restrict__ in, float* __restrict__ out, int n_octs) {
    __shared__ __align__(16) float sbuf[2][NROWS][SSTRIDE];

    const int tid = threadIdx.x;
    const int lane = tid & 31;
    const int wid = tid >> 5;

    // Zero the pad columns of every smem row (left 4 + right 4) once.
    for (int i = tid; i < 2 * NROWS; i += 128) {
        int b = i / NROWS, r = i % NROWS;
        *(float4*)&sbuf[b][r][0]   = make_float4(0.f, 0.f, 0.f, 0.f);
        *(float4*)&sbuf[b][r][516] = make_float4(0.f, 0.f, 0.f, 0.f);
    }

    // Stage loader: oct -> buffer b. Rows y0-1 .. y0+8; OOB rows become zeros.
    auto load_stage = [&](int b, int oct) {
        const int img = oct >> 6;
        const int y0 = (oct & 63) << 3;
        const float* __restrict__ base = in + (size_t)img * (H * W);
#pragma unroll
        for (int r = 0; r < NROWS; r++) {
            const int gy = y0 - 1 + r;
            float* dst = &sbuf[b][r][DATA0 + tid * 4];
            if ((unsigned)gy < (unsigned)H) {
                __pipeline_memcpy_async(dst, base + gy * W + tid * 4, 16);
            } else {
                *(float4*)dst = make_float4(0.f, 0.f, 0.f, 0.f);
            }
        }
    };

    // Compute one oct from buffer b: warp -> (quad, 256-col half); R5 network.
    auto compute_stage = [&](int b, int oct) {
        const int img = oct >> 6;
        const int y0 = (oct & 63) << 3;
        float* __restrict__ obase = out + (size_t)img * (H * W);
        const int qw = wid >> 1;                    // quad 0/1
        const int c0 = ((wid & 1) << 8) + (lane << 3);
        const bool isL = (lane == 0);
        const bool isR = (lane == 31);
        const int eidx = isL ? (DATA0 + c0 - 1) : (DATA0 + c0 + 8);
        const int yq = y0 + qw * 4;

        float4 v[12];
        float e[6];
#pragma unroll
        for (int k = 0; k < 6; k++) {
            const float* srow = &sbuf[b][qw * 4 + k][0];
            v[2 * k]     = *(const float4*)(srow + DATA0 + c0);
            v[2 * k + 1] = *(const float4*)(srow + DATA0 + c0 + 4);
            e[k] = srow[eidx];                      // unconditional (pads are zero)
        }

        float r2[8] = {v[4].x, v[4].y, v[4].z, v[4].w, v[5].x, v[5].y, v[5].z, v[5].w};
        float r3[8] = {v[6].x, v[6].y, v[6].z, v[6].w, v[7].x, v[7].y, v[7].z, v[7].w};
        float p[8], q[8];
        {
            float r1[8] = {v[2].x, v[2].y, v[2].z, v[2].w, v[3].x, v[3].y, v[3].z, v[3].w};
#pragma unroll
            for (int i = 0; i < 8; i++) {
                p[i] = fminf(r1[i], r2[i]);
                q[i] = fmaxf(r1[i], r2[i]);
            }
        }
        {
            const float epA = fminf(e[1], e[2]), eqA = fmaxf(e[1], e[2]);
            float t0[8] = {v[0].x, v[0].y, v[0].z, v[0].w, v[1].x, v[1].y, v[1].z, v[1].w};
            do_row(t0, p, q, e[0], epA, eqA, isL, isR, obase + (yq    ) * W, c0);
            do_row(r3, p, q, e[3], epA, eqA, isL, isR, obase + (yq + 1) * W, c0);
        }
        {
            float r4[8] = {v[8].x, v[8].y, v[8].z, v[8].w, v[9].x, v[9].y, v[9].z, v[9].w};
#pragma unroll
            for (int i = 0; i < 8; i++) {
                float mn = fminf(r3[i], r4[i]);
                float mx = fmaxf(r3[i], r4[i]);
                p[i] = mn;
                q[i] = mx;
            }
        }
        {
            const float epB = fminf(e[3], e[4]), eqB = fmaxf(e[3], e[4]);
            do_row(r2, p, q, e[2], epB, eqB, isL, isR, obase + (yq + 2) * W, c0);
            float t5[8] = {v[10].x, v[10].y, v[10].z, v[10].w, v[11].x, v[11].y, v[11].z, v[11].w};
            do_row(t5, p, q, e[5], epB, eqB, isL, isR, obase + (yq + 3) * W, c0);
        }
    };

    const int stride = gridDim.x;
    const int oct0 = blockIdx.x;

    // Prologue: two stages in flight (double buffer, depth-1 overlap).
    if (oct0 < n_octs) load_stage(0, oct0);
    __pipeline_commit();
    if (oct0 + stride < n_octs) load_stage(1, oct0 + stride);
    __pipeline_commit();

    int it = 0;
    for (int o = oct0; o < n_octs; o += stride, it++) {
        __pipeline_wait_prior(1);      // this stage's group complete
        __syncthreads();               // smem visible to all warps
        compute_stage(it & 1, o);
        __syncthreads();               // everyone done reading before refill
        const int onext = o + 2 * stride;
        if (onext < n_octs) load_stage(it & 1, onext);
        __pipeline_commit();           // always commit to keep group count consistent
    }
}

extern "C" void kernel_launch(void* const* d_in, const int* in_sizes, int n_in,
                              void* d_out, int out_size) {
    const float* x = (const float*)d_in[0];
    float* y = (float*)d_out;
    const int nimg = in_sizes[0] / (H * W);    // B*C images
    const int n_octs = nimg * (H / 8);         // 8 output rows per oct
    const int grid = 2048;                     // persistent-strided CTAs
    median3x3_kernel<<<grid, 128>>>(x, y, n_octs);
}

// round 12
// speedup vs baseline: 1.0078x; 1.0078x over previous
#include <cuda_runtime.h>

static constexpr int H = 512;
static constexpr int W = 512;
static constexpr unsigned FULL = 0xFFFFFFFFu;
static constexpr int NQ = 4;     // quads (4 output rows each) per warp

__device__ __forceinline__ float med3f(float a, float b, float c) {
    return fmaxf(fminf(a, b), fminf(fmaxf(a, b), c));
}

// Horizontal merge for 8 outputs of one row.
// lo/md/hi: [L-edge, 8 own columns, R-edge], each vertically sorted.
// Pair (2k+1, 2k+2) is shared by windows 2k and 2k+1.
__device__ __forceinline__ void hmerge8(const float* lo, const float* md,
                                         const float* hi, float* o) {
#pragma unroll
    for (int k = 0; k < 4; k++) {
        float pxl = fmaxf(lo[2 * k + 1], lo[2 * k + 2]);
        float pzl = fminf(hi[2 * k + 1], hi[2 * k + 2]);
        float mn  = fminf(md[2 * k + 1], md[2 * k + 2]);
        float mx  = fmaxf(md[2 * k + 1], md[2 * k + 2]);
        float X0 = fmaxf(lo[2 * k], pxl);
        float X1 = fmaxf(pxl, lo[2 * k + 3]);
        float Z0 = fminf(hi[2 * k], pzl);
        float Z1 = fminf(pzl, hi[2 * k + 3]);
        float Y0 = fmaxf(mn, fminf(mx, md[2 * k]));
        float Y1 = fmaxf(mn, fminf(mx, md[2 * k + 3]));
        o[2 * k]     = med3f(X0, Y0, Z0);
        o[2 * k + 1] = med3f(X1, Y1, Z1);
    }
}

// Merge row t into pre-sorted pair (p,q), exchange edge triples, merge, store one row.
__device__ __forceinline__ void do_row(const float* t, const float* p, const float* q,
                                        float et, float ep, float eq,
                                        bool isL, bool isR,
                                        float* __restrict__ orow, int c0) {
    float lo[10], md[10], hi[10];
#pragma unroll
    for (int i = 0; i < 8; i++) {
        float m = fmaxf(t[i], p[i]);
        lo[i + 1] = fminf(t[i], p[i]);
        hi[i + 1] = fmaxf(m, q[i]);
        md[i + 1] = fminf(m, q[i]);
    }
    float em = fmaxf(et, ep);
    float elo = fminf(et, ep), ehi = fmaxf(em, eq), emd = fminf(em, eq);
    float Ll = __shfl_up_sync(FULL, lo[8], 1);
    float Lm = __shfl_up_sync(FULL, md[8], 1);
    float Lh = __shfl_up_sync(FULL, hi[8], 1);
    float Rl = __shfl_down_sync(FULL, lo[1], 1);
    float Rm = __shfl_down_sync(FULL, md[1], 1);
    float Rh = __shfl_down_sync(FULL, hi[1], 1);
    lo[0] = isL ? elo : Ll;  md[0] = isL ? emd : Lm;  hi[0] = isL ? ehi : Lh;
    lo[9] = isR ? elo : Rl;  md[9] = isR ? emd : Rm;  hi[9] = isR ? ehi : Rh;
    float o[8];
    hmerge8(lo, md, hi, o);
    *(float4*)(orow + c0)     = make_float4(o[0], o[1], o[2], o[3]);
    *(float4*)(orow + c0 + 4) = make_float4(o[4], o[5], o[6], o[7]);
}

__global__ __launch_bounds__(128)
void median3x3_kernel(const float* __restrict__ in, float* __restrict__ out, int nimg) {
    const int gwarp = (blockIdx.x * blockDim.x + threadIdx.x) >> 5;
    const int lane = threadIdx.x & 31;

    // Per image: (H / (4*NQ)) y-groups x 2 column halves. Warp loops NQ quads.
    const int groupsY = H / (4 * NQ);                      // 32
    const int img = gwarp / (groupsY * 2);
    if (img >= nimg) return;
    const int rem = gwarp % (groupsY * 2);
    const int ybase = (rem >> 1) * (4 * NQ);               // 0,16,...,496
    const int c0 = ((rem & 1) << 8) + (lane << 3);         // 8 columns per lane

    const float* __restrict__ base = in + (size_t)img * (H * W);
    float* __restrict__ obase = out + (size_t)img * (H * W);

    const bool isL = (lane == 0);
    const bool isR = (lane == 31);
    const int ecol = isL ? (c0 - 1) : (c0 + 8);
    const bool ev = (isL | isR) && ((unsigned)ecol < (unsigned)W);
    const float4 zero4 = make_float4(0.f, 0.f, 0.f, 0.f);

#pragma unroll 1
    for (int iq = 0; iq < NQ; iq++) {
        const int y0 = ybase + 4 * iq;
        const bool topOK = (y0 > 0);
        const bool botOK = (y0 + 4 < H);

        // ---- Load 6 input rows (y0-1 .. y0+4) x 8 cols: 12 x LDG.128 front-batched ----
        float4 i0a = topOK ? *(const float4*)(base + (y0 - 1) * W + c0)     : zero4;
        float4 i0b = topOK ? *(const float4*)(base + (y0 - 1) * W + c0 + 4) : zero4;
        float4 i1a =         *(const float4*)(base + (y0    ) * W + c0);
        float4 i1b =         *(const float4*)(base + (y0    ) * W + c0 + 4);
        float4 i2a =         *(const float4*)(base + (y0 + 1) * W + c0);
        float4 i2b =         *(const float4*)(base + (y0 + 1) * W + c0 + 4);
        float4 i3a =         *(const float4*)(base + (y0 + 2) * W + c0);
        float4 i3b =         *(const float4*)(base + (y0 + 2) * W + c0 + 4);
        float4 i4a =         *(const float4*)(base + (y0 + 3) * W + c0);
        float4 i4b =         *(const float4*)(base + (y0 + 3) * W + c0 + 4);
        float4 i5a = botOK ? *(const float4*)(base + (y0 + 4) * W + c0)     : zero4;
        float4 i5b = botOK ? *(const float4*)(base + (y0 + 4) * W + c0 + 4) : zero4;

        // Warp-edge boundary column (6 rows), lanes 0/31 only.
        float e0 = (ev && topOK) ? base[(y0 - 1) * W + ecol] : 0.f;
        float e1 = ev            ? base[(y0    ) * W + ecol] : 0.f;
        float e2 = ev            ? base[(y0 + 1) * W + ecol] : 0.f;
        float e3 = ev            ? base[(y0 + 2) * W + ecol] : 0.f;
        float e4 = ev            ? base[(y0 + 3) * W + ecol] : 0.f;
        float e5 = (ev && botOK) ? base[(y0 + 4) * W + ecol] : 0.f;

        float r2[8] = {i2a.x, i2a.y, i2a.z, i2a.w, i2b.x, i2b.y, i2b.z, i2b.w};
        float r3[8] = {i3a.x, i3a.y, i3a.z, i3a.w, i3b.x, i3b.y, i3b.z, i3b.w};

        // ---- Pair A = sort(i1, i2); i1 dies here ----
        float p[8], q[8];
        {
            float r1[8] = {i1a.x, i1a.y, i1a.z, i1a.w, i1b.x, i1b.y, i1b.z, i1b.w};
#pragma unroll
            for (int i = 0; i < 8; i++) {
                p[i] = fminf(r1[i], r2[i]);
                q[i] = fmaxf(r1[i], r2[i]);
            }
        }
        {
            const float epA = fminf(e1, e2), eqA = fmaxf(e1, e2);
            // Rows o0 = (i0, i1, i2), o1 = (i1, i2, i3) via shared pair A.
            float t0[8] = {i0a.x, i0a.y, i0a.z, i0a.w, i0b.x, i0b.y, i0b.z, i0b.w};
            do_row(t0, p, q, e0, epA, eqA, isL, isR, obase + (y0    ) * W, c0);
            do_row(r3, p, q, e3, epA, eqA, isL, isR, obase + (y0 + 1) * W, c0);
        }

        // ---- Pair B = sort(i3, i4); reuse p,q storage ----
        {
            float r4[8] = {i4a.x, i4a.y, i4a.z, i4a.w, i4b.x, i4b.y, i4b.z, i4b.w};
#pragma unroll
            for (int i = 0; i < 8; i++) {
                float mn = fminf(r3[i], r4[i]);
                float mx = fmaxf(r3[i], r4[i]);
                p[i] = mn;
                q[i] = mx;
            }
        }
        {
            const float epB = fminf(e3, e4), eqB = fmaxf(e3, e4);
            // Rows o2 = (i2, i3, i4), o3 = (i3, i4, i5) via shared pair B.
            do_row(r2, p, q, e2, epB, eqB, isL, isR, obase + (y0 + 2) * W, c0);
            float t5[8] = {i5a.x, i5a.y, i5a.z, i5a.w, i5b.x, i5b.y, i5b.z, i5b.w};
            do_row(t5, p, q, e5, epB, eqB, isL, isR, obase + (y0 + 3) * W, c0);
        }
    }
}

extern "C" void kernel_launch(void* const* d_in, const int* in_sizes, int n_in,
                              void* d_out, int out_size) {
    const float* x = (const float*)d_in[0];
    float* y = (float*)d_out;
    const int nimg = in_sizes[0] / (H * W);                  // B*C images
    const int warps = nimg * (H / (4 * NQ)) * 2;             // y-groups x 2 halves
    const int threads = warps * 32;
    const int block = 128;
    const int grid = (threads + block - 1) / block;
    median3x3_kernel<<<grid, block>>>(x, y, nimg);
}